// round 1
// baseline (speedup 1.0000x reference)
#include <cuda_runtime.h>
#include <cstdint>

#define BB 32
#define HH 128
#define WW 128
#define NPIX 16384            // 128*128
#define WIDTH 64
#define M1 20
#define M2 20

// ---------------- scratch (device globals; no runtime allocation) ----------------
__device__ float g_x [ (size_t)BB*WIDTH*NPIX ];   // current state (B,64,H,W)
__device__ float g_x1[ (size_t)BB*WIDTH*NPIX ];   // spectral branch out
__device__ float g_x2[ (size_t)BB*WIDTH*NPIX ];   // conv branch out
__device__ float g_y1[ (size_t)BB*WIDTH*128*40 ]; // fwd W-DFT: (b,c,h, [20 re | 20 im])
__device__ float g_z [ (size_t)BB*WIDTH*1600 ];   // fwd H-DFT: (b,c, [800 re | 800 im]) over (kx40,ky20)
__device__ float g_zo[ (size_t)BB*WIDTH*1600 ];   // after mode mixing
__device__ float g_u [ (size_t)BB*WIDTH*5120 ];   // inv H: (b,o,h,[20 re|20 im])
__device__ float g_Tf [40*128];                   // rows 0..19: cos(2pi w k/128); 20..39: -sin
__device__ float g_ThC[40*128];                   // cos(2pi h kx/128), kx in {0..19,108..127}
__device__ float g_ThS[40*128];                   // sin(...)

__device__ __forceinline__ float gelu_t(float x) {
    // jax.nn.gelu default (approximate=True, tanh form)
    float x3 = x * x * x;
    return 0.5f * x * (1.0f + tanhf(0.7978845608028654f * (x + 0.044715f * x3)));
}

// ---------------- twiddle tables ----------------
__global__ void k_init_tables() {
    for (int i = threadIdx.x + blockIdx.x * blockDim.x; i < 40 * 128; i += blockDim.x * gridDim.x) {
        int k = i / 128, w = i % 128;
        float s, c;
        if (k < 20) {
            sincospif((float)((w * k) & 127) / 64.0f, &s, &c);
            g_Tf[i] = c;
        } else {
            sincospif((float)((w * (k - 20)) & 127) / 64.0f, &s, &c);
            g_Tf[i] = -s;
        }
        int kxv = (k < 20) ? k : (108 + (k - 20));
        sincospif((float)((w * kxv) & 127) / 64.0f, &s, &c);
        g_ThC[i] = c;
        g_ThS[i] = s;
    }
}

// ---------------- lift: grid + quadpath + fc0 MLP -> g_x (B,64,H,W) ----------------
__global__ void __launch_bounds__(128) k_lift(
    const float* __restrict__ xin, const float* __restrict__ qa, const float* __restrict__ qb,
    const float* __restrict__ w1, const float* __restrict__ b1,
    const float* __restrict__ w2, const float* __restrict__ b2)
{
    __shared__ float qas[48], qbs[48], b2s[48];
    __shared__ float w1s[128 * 16];
    __shared__ float b1s[128];
    __shared__ float w2t[128 * 48];  // transposed: [m][o]
    int tid = threadIdx.x;
    if (tid < 48) { qas[tid] = qa[tid]; qbs[tid] = qb[tid]; b2s[tid] = b2[tid]; }
    b1s[tid] = b1[tid];
    for (int i = tid; i < 2048; i += 128) w1s[i] = w1[i];
    for (int i = tid; i < 6144; i += 128) { int o = i / 128, m = i % 128; w2t[m * 48 + o] = w2[i]; }
    __syncthreads();

    int p = blockIdx.x * 128 + tid;
    int b = p >> 14, pix = p & 16383;
    int h = pix >> 7, w = pix & 127;

    float f[16];
    const float* xp = xin + ((size_t)b * 10) * NPIX + pix;
#pragma unroll
    for (int c = 0; c < 10; c++) f[c] = xp[(size_t)c * NPIX];
    f[10] = (float)h * (1.0f / 127.0f);
    f[11] = (float)w * (1.0f / 127.0f);
#pragma unroll
    for (int j = 0; j < 4; j++) {
        float sa = 0.f, sb = 0.f;
#pragma unroll
        for (int c = 0; c < 12; c++) { sa += qas[j * 12 + c] * f[c]; sb += qbs[j * 12 + c] * f[c]; }
        f[12 + j] = sa * sb;
    }
    float acc[48];
#pragma unroll
    for (int o = 0; o < 48; o++) acc[o] = b2s[o];
    for (int m = 0; m < 128; m++) {
        float t = b1s[m];
#pragma unroll
        for (int c = 0; c < 16; c++) t += w1s[m * 16 + c] * f[c];
        float g = gelu_t(t);
#pragma unroll
        for (int o4 = 0; o4 < 12; o4++) {
            float4 wv = *(const float4*)&w2t[m * 48 + o4 * 4];
            acc[o4 * 4 + 0] += wv.x * g; acc[o4 * 4 + 1] += wv.y * g;
            acc[o4 * 4 + 2] += wv.z * g; acc[o4 * 4 + 3] += wv.w * g;
        }
    }
    float* op = g_x + ((size_t)b * WIDTH) * NPIX + pix;
#pragma unroll
    for (int c = 0; c < 16; c++) op[(size_t)c * NPIX] = f[c];
#pragma unroll
    for (int o = 0; o < 48; o++) op[(size_t)(16 + o) * NPIX] = acc[o];
}

// ---------------- forward partial rfft along W ----------------
// rows: (b,c,h) flattened = 262144.  out[row][k<20]=Re, [20..39]=Im
__global__ void __launch_bounds__(256) k_fwdW() {
    __shared__ float xs[32][128];
    __shared__ float tf[128][40];
    int row0 = blockIdx.x * 32;
    for (int i = threadIdx.x; i < 32 * 128; i += 256)
        xs[i / 128][i % 128] = g_x[(size_t)row0 * 128 + i];
    for (int i = threadIdx.x; i < 40 * 128; i += 256) {
        int k = i / 128, w = i % 128;
        tf[w][k] = g_Tf[i];
    }
    __syncthreads();
    for (int u = threadIdx.x; u < 320; u += 256) {
        int r = u / 10, kg = (u % 10) * 4;
        float s0 = 0.f, s1 = 0.f, s2 = 0.f, s3 = 0.f;
#pragma unroll 8
        for (int w = 0; w < 128; w++) {
            float xv = xs[r][w];
            float4 t = *(const float4*)&tf[w][kg];
            s0 += xv * t.x; s1 += xv * t.y; s2 += xv * t.z; s3 += xv * t.w;
        }
        float4 o; o.x = s0; o.y = s1; o.z = s2; o.w = s3;
        *(float4*)&g_y1[(size_t)(row0 + r) * 40 + kg] = o;
    }
}

// ---------------- forward full DFT along H at the 40 kept kx ----------------
__global__ void __launch_bounds__(256) k_fwdH() {
    __shared__ float ys[128][40];
    int bc = blockIdx.x;
    const float* src = g_y1 + (size_t)bc * 5120;
    for (int i = threadIdx.x; i < 5120; i += 256) ys[i / 40][i % 40] = src[i];
    __syncthreads();
    for (int o = threadIdx.x; o < 800; o += 256) {
        int kx = o / 20, ky = o % 20;
        float zr = 0.f, zi = 0.f;
#pragma unroll 4
        for (int h = 0; h < 128; h++) {
            float c = g_ThC[kx * 128 + h], s = g_ThS[kx * 128 + h];
            float yr = ys[h][ky], yi = ys[h][20 + ky];
            zr += yr * c + yi * s;
            zi += yi * c - yr * s;
        }
        g_z[(size_t)bc * 1600 + o] = zr;
        g_z[(size_t)bc * 1600 + 800 + o] = zi;
    }
}

// ---------------- per-mode complex channel mixing ----------------
__global__ void __launch_bounds__(256) k_mix(
    const float* __restrict__ sw1r, const float* __restrict__ sw1i,
    const float* __restrict__ sw2r, const float* __restrict__ sw2i, int layer)
{
    __shared__ float Wr[64][64], Wi[64][64];
    __shared__ float Zr[4][64], Zi[4][64];
    int m = blockIdx.x;
    int kxi = m / 20, ky = m % 20;
    const float* wr; const float* wi; int kxm;
    if (kxi < 20) { wr = sw1r; wi = sw1i; kxm = kxi; }
    else          { wr = sw2r; wi = sw2i; kxm = kxi - 20; }
    size_t base = (size_t)layer * 64 * 64 * 400;
    for (int i = threadIdx.x; i < 4096; i += 256) {
        int ii = i / 64, oo = i % 64;
        size_t idx = base + (size_t)(ii * 64 + oo) * 400 + kxm * 20 + ky;
        Wr[ii][oo] = wr[idx]; Wi[ii][oo] = wi[idx];
    }
    int oo = threadIdx.x & 63, bb = threadIdx.x >> 6;
    for (int b0 = 0; b0 < 32; b0 += 4) {
        __syncthreads();
        for (int i = threadIdx.x; i < 256; i += 256) {
            int lb = i / 64, c = i % 64;
            size_t zb = ((size_t)(b0 + lb) * 64 + c) * 1600 + kxi * 20 + ky;
            Zr[lb][c] = g_z[zb]; Zi[lb][c] = g_z[zb + 800];
        }
        __syncthreads();
        float orr = 0.f, oii = 0.f;
#pragma unroll 8
        for (int i2 = 0; i2 < 64; i2++) {
            float zr = Zr[bb][i2], zi = Zi[bb][i2];
            float wrv = Wr[i2][oo], wiv = Wi[i2][oo];
            orr += zr * wrv - zi * wiv;
            oii += zr * wiv + zi * wrv;
        }
        size_t ob = ((size_t)(b0 + bb) * 64 + oo) * 1600 + kxi * 20 + ky;
        g_zo[ob] = orr; g_zo[ob + 800] = oii;
    }
}

// ---------------- inverse DFT along H (unnormalized) ----------------
__global__ void __launch_bounds__(256) k_invH() {
    __shared__ float zs[1600];
    int bo = blockIdx.x;
    for (int i = threadIdx.x; i < 1600; i += 256) zs[i] = g_zo[(size_t)bo * 1600 + i];
    __syncthreads();
    for (int o = threadIdx.x; o < 2560; o += 256) {
        int h = o / 20, ky = o % 20;
        float ur = 0.f, ui = 0.f;
#pragma unroll 8
        for (int kx = 0; kx < 40; kx++) {
            float c = g_ThC[kx * 128 + h], s = g_ThS[kx * 128 + h];
            float zr = zs[kx * 20 + ky], zi = zs[800 + kx * 20 + ky];
            ur += zr * c - zi * s;
            ui += zr * s + zi * c;
        }
        g_u[(size_t)bo * 5120 + h * 40 + ky]      = ur;
        g_u[(size_t)bo * 5120 + h * 40 + 20 + ky] = ui;
    }
}

// ---------------- inverse rfft along W, scale 1/(H*W) ----------------
__global__ void __launch_bounds__(256) k_invW() {
    __shared__ float us[128][40];
    __shared__ float tfs[40][128];
    int bo = blockIdx.x;
    for (int i = threadIdx.x; i < 5120; i += 256) us[i / 40][i % 40] = g_u[(size_t)bo * 5120 + i];
    for (int i = threadIdx.x; i < 40 * 128; i += 256) ((float*)tfs)[i] = g_Tf[i];
    __syncthreads();
    const float inv = 1.0f / 16384.0f;
    for (int u = threadIdx.x; u < 4096; u += 256) {
        int h = u >> 5, w4 = (u & 31) * 4;
        float a0 = 0.f, a1 = 0.f, a2 = 0.f, a3 = 0.f;
#pragma unroll
        for (int ky = 1; ky < 20; ky++) {
            float ur = us[h][ky], ui = us[h][20 + ky];
            float4 c4 = *(const float4*)&tfs[ky][w4];
            float4 s4 = *(const float4*)&tfs[20 + ky][w4];
            a0 += ur * c4.x + ui * s4.x;
            a1 += ur * c4.y + ui * s4.y;
            a2 += ur * c4.z + ui * s4.z;
            a3 += ur * c4.w + ui * s4.w;
        }
        float dc = us[h][0];  // ky=0: imag part dropped by C2R
        float4 o;
        o.x = (dc + 2.f * a0) * inv;
        o.y = (dc + 2.f * a1) * inv;
        o.z = (dc + 2.f * a2) * inv;
        o.w = (dc + 2.f * a3) * inv;
        *(float4*)&g_x1[(size_t)bo * NPIX + h * 128 + w4] = o;
    }
}

// ---------------- circular 3x3 conv ----------------
__global__ void __launch_bounds__(256) k_conv(
    const float* __restrict__ cw, const float* __restrict__ cb, int layer)
{
    __shared__ float tile[18][18];
    __shared__ float wshT[9][16];
    int b = blockIdx.z >> 2, ocg = blockIdx.z & 3;
    int h0 = blockIdx.y * 16, w0 = blockIdx.x * 16;
    int tx = threadIdx.x, ty = threadIdx.y;
    int tid = ty * 16 + tx;
    float acc[16];
#pragma unroll
    for (int j = 0; j < 16; j++) acc[j] = cb[layer * 64 + ocg * 16 + j];
    const float* xin = g_x + (size_t)b * WIDTH * NPIX;
    for (int cin = 0; cin < 64; cin++) {
        __syncthreads();
        for (int i = tid; i < 324; i += 256) {
            int r = i / 18, cc = i % 18;
            int gh = (h0 + r - 1) & 127, gw = (w0 + cc - 1) & 127;
            tile[r][cc] = xin[(size_t)cin * NPIX + gh * 128 + gw];
        }
        if (tid < 144) {
            int k = tid / 16, j = tid % 16;
            wshT[k][j] = cw[(((size_t)layer * 64 + ocg * 16 + j) * 64 + cin) * 9 + k];
        }
        __syncthreads();
        float v[9];
#pragma unroll
        for (int dy = 0; dy < 3; dy++)
#pragma unroll
            for (int dx = 0; dx < 3; dx++) v[dy * 3 + dx] = tile[ty + dy][tx + dx];
#pragma unroll
        for (int k = 0; k < 9; k++) {
            float vk = v[k];
#pragma unroll
            for (int j4 = 0; j4 < 4; j4++) {
                float4 wv = *(const float4*)&wshT[k][j4 * 4];
                acc[j4 * 4 + 0] += wv.x * vk; acc[j4 * 4 + 1] += wv.y * vk;
                acc[j4 * 4 + 2] += wv.z * vk; acc[j4 * 4 + 3] += wv.w * vk;
            }
        }
    }
    size_t outb = ((size_t)b * 64 + ocg * 16) * NPIX + (h0 + ty) * 128 + (w0 + tx);
#pragma unroll
    for (int j = 0; j < 16; j++) g_x2[outb + (size_t)j * NPIX] = acc[j];
}

// ---------------- product features + pointwise mix + tanh residual ----------------
__global__ void __launch_bounds__(128) k_combine(
    const float* __restrict__ pw, const float* __restrict__ pb, int layer)
{
    __shared__ float ws[64 * 132];  // padded stride 132 for float4 alignment
    __shared__ float bs[64];
    int tid = threadIdx.x;
    for (int i = tid; i < 64 * 130; i += 128) { int o = i / 130, c = i % 130; ws[o * 132 + c] = pw[(size_t)layer * 8320 + i]; }
    if (tid < 64) bs[tid] = pb[layer * 64 + tid];
    __syncthreads();
    int p = blockIdx.x * 128 + tid;
    int b = p >> 14, pix = p & 16383;
    const float* x1p = g_x1 + ((size_t)b * 64) * NPIX + pix;
    const float* x2p = g_x2 + ((size_t)b * 64) * NPIX + pix;
    float acc[64];
#pragma unroll
    for (int o = 0; o < 64; o++) acc[o] = bs[o];
    float sa0 = 0.f, sa1 = 0.f, sa2 = 0.f, sa3 = 0.f;
    for (int c4 = 0; c4 < 64; c4 += 4) {
        float a0 = x1p[(size_t)(c4 + 0) * NPIX], a1 = x1p[(size_t)(c4 + 1) * NPIX];
        float a2 = x1p[(size_t)(c4 + 2) * NPIX], a3 = x1p[(size_t)(c4 + 3) * NPIX];
        float d0 = x2p[(size_t)(c4 + 0) * NPIX], d1 = x2p[(size_t)(c4 + 1) * NPIX];
        float d2 = x2p[(size_t)(c4 + 2) * NPIX], d3 = x2p[(size_t)(c4 + 3) * NPIX];
        if (c4 == 0) { sa0 = a0; sa1 = a1; sa2 = a2; sa3 = a3; }
#pragma unroll
        for (int o = 0; o < 64; o++) {
            float4 wa = *(const float4*)&ws[o * 132 + c4];
            float4 wd = *(const float4*)&ws[o * 132 + 64 + c4];
            acc[o] += wa.x * a0 + wa.y * a1 + wa.z * a2 + wa.w * a3
                    + wd.x * d0 + wd.y * d1 + wd.z * d2 + wd.w * d3;
        }
    }
    float p0 = sa0 * sa2, p1 = sa1 * sa3;
    float* xp = g_x + ((size_t)b * 64) * NPIX + pix;
#pragma unroll
    for (int o = 0; o < 64; o++) {
        float t = acc[o] + ws[o * 132 + 128] * p0 + ws[o * 132 + 129] * p1;
        xp[(size_t)o * NPIX] += tanhf(t);
    }
}

// ---------------- final projection MLP ----------------
__global__ void __launch_bounds__(128) k_final(
    const float* __restrict__ w1, const float* __restrict__ b1,
    const float* __restrict__ w2, const float* __restrict__ b2,
    float* __restrict__ out)
{
    __shared__ float w1s[128 * 64];
    __shared__ float b1s[128], w2s[128];
    int tid = threadIdx.x;
    for (int i = tid; i < 8192; i += 128) w1s[i] = w1[i];
    b1s[tid] = b1[tid];
    w2s[tid] = w2[tid];
    __syncthreads();
    int p = blockIdx.x * 128 + tid;
    int b = p >> 14, pix = p & 16383;
    const float* xp = g_x + ((size_t)b * 64) * NPIX + pix;
    float xv[64];
#pragma unroll
    for (int c = 0; c < 64; c++) xv[c] = xp[(size_t)c * NPIX];
    float acc = b2[0];
    for (int m = 0; m < 128; m++) {
        float t = b1s[m];
#pragma unroll
        for (int c4 = 0; c4 < 16; c4++) {
            float4 wv = *(const float4*)&w1s[m * 64 + c4 * 4];
            t += wv.x * xv[c4 * 4] + wv.y * xv[c4 * 4 + 1] + wv.z * xv[c4 * 4 + 2] + wv.w * xv[c4 * 4 + 3];
        }
        acc += w2s[m] * gelu_t(t);
    }
    out[p] = acc;
}

// ---------------- launch ----------------
extern "C" void kernel_launch(void* const* d_in, const int* in_sizes, int n_in,
                              void* d_out, int out_size)
{
    const float* x      = (const float*)d_in[0];
    const float* qa     = (const float*)d_in[1];
    const float* qb     = (const float*)d_in[2];
    const float* fc0_w1 = (const float*)d_in[3];
    const float* fc0_b1 = (const float*)d_in[4];
    const float* fc0_w2 = (const float*)d_in[5];
    const float* fc0_b2 = (const float*)d_in[6];
    const float* sw1r   = (const float*)d_in[7];
    const float* sw1i   = (const float*)d_in[8];
    const float* sw2r   = (const float*)d_in[9];
    const float* sw2i   = (const float*)d_in[10];
    const float* cw     = (const float*)d_in[11];
    const float* cb     = (const float*)d_in[12];
    const float* pw     = (const float*)d_in[13];
    const float* pb     = (const float*)d_in[14];
    const float* fc1_w1 = (const float*)d_in[15];
    const float* fc1_b1 = (const float*)d_in[16];
    const float* fc1_w2 = (const float*)d_in[17];
    const float* fc1_b2 = (const float*)d_in[18];
    float* out = (float*)d_out;

    k_init_tables<<<20, 256>>>();
    k_lift<<<4096, 128>>>(x, qa, qb, fc0_w1, fc0_b1, fc0_w2, fc0_b2);

    for (int layer = 0; layer < 4; layer++) {
        k_fwdW<<<8192, 256>>>();
        k_fwdH<<<2048, 256>>>();
        k_mix<<<800, 256>>>(sw1r, sw1i, sw2r, sw2i, layer);
        k_invH<<<2048, 256>>>();
        k_invW<<<2048, 256>>>();
        k_conv<<<dim3(8, 8, 128), dim3(16, 16)>>>(cw, cb, layer);
        k_combine<<<4096, 128>>>(pw, pb, layer);
    }

    k_final<<<4096, 128>>>(fc1_w1, fc1_b1, fc1_w2, fc1_b2, out);
}